// round 14
// baseline (speedup 1.0000x reference)
#include <cuda_runtime.h>
#include <string.h>

#define BATCH 128
#define TLEN  8192
#define HDIM  96
#define NTHR  384   // 12 gate warps, exactly 3 per SMSP; y done in post-pass

// h history for the y post-pass (device global: the documented no-alloc workaround)
__device__ float g_hist[(size_t)BATCH * TLEN * HDIM];

// Packed fp32x2 FMA (Blackwell): rt=2/SMSP, 2 MACs per issue.
#define FMA2(d, a, b, c) \
    asm("fma.rn.f32x2 %0, %1, %2, %3;" : "=l"(d) : "l"(a), "l"(b), "l"(c))
#define ADD2(d, a, b) \
    asm("add.rn.f32x2 %0, %1, %2;" : "=l"(d) : "l"(a), "l"(b))
#define UNPACK2(lo, hi, v) \
    asm("mov.b64 {%0, %1}, %2;" : "=f"(lo), "=f"(hi) : "l"(v))

__device__ __forceinline__ float ex2_fast(float x) {
    float y; asm("ex2.approx.f32 %0, %1;" : "=f"(y) : "f"(x)); return y;
}
__device__ __forceinline__ float rcp_fast(float x) {
    float y; asm("rcp.approx.f32 %0, %1;" : "=f"(y) : "f"(x)); return y;
}
__device__ __forceinline__ void cta_bar() {
    asm volatile("bar.sync 0;" ::: "memory");
}
// predicated global store (q==0 sublane only): no BSSY/BSYNC
__device__ __forceinline__ void stg_pred(int pred_q, float* addr, float v) {
    asm volatile(
        "{ .reg .pred p; setp.eq.s32 p, %0, 0; @p st.global.f32 [%1], %2; }"
        :: "r"(pred_q), "l"(addr), "f"(v) : "memory");
}

#define LOG2E 1.4426950408889634f

// One LSTM step (byte-identical math to the R12 champion).
// XOR-permuted slots + 2-stage select-free butterfly + scaled-C domain.
__device__ __forceinline__ void lstm_step(
    const float* __restrict__ hin, float* __restrict__ hout,
    float* __restrict__ hist_t, float pre,
    const ulonglong2 (&wreg)[4][6], float Aq, float Bq,
    int base, int u, int q, float& C)
{
    const ulonglong2* hq = (const ulonglong2*)hin;   // hin already offset by 24q
    ulonglong2 h0 = hq[0], h1 = hq[1], h2v = hq[2];
    ulonglong2 h3 = hq[3], h4 = hq[4], h5 = hq[5];

    unsigned long long acc[4][2];
    #pragma unroll
    for (int s = 0; s < 4; s++) { acc[s][0] = 0ull; acc[s][1] = 0ull; }
    #pragma unroll
    for (int s = 0; s < 4; s++) {
        FMA2(acc[s][0], wreg[s][0].x, h0.x, acc[s][0]);
        FMA2(acc[s][1], wreg[s][0].y, h0.y, acc[s][1]);
        FMA2(acc[s][0], wreg[s][1].x, h1.x, acc[s][0]);
        FMA2(acc[s][1], wreg[s][1].y, h1.y, acc[s][1]);
        FMA2(acc[s][0], wreg[s][2].x, h2v.x, acc[s][0]);
        FMA2(acc[s][1], wreg[s][2].y, h2v.y, acc[s][1]);
        FMA2(acc[s][0], wreg[s][3].x, h3.x, acc[s][0]);
        FMA2(acc[s][1], wreg[s][3].y, h3.y, acc[s][1]);
        FMA2(acc[s][0], wreg[s][4].x, h4.x, acc[s][0]);
        FMA2(acc[s][1], wreg[s][4].y, h4.y, acc[s][1]);
        FMA2(acc[s][0], wreg[s][5].x, h5.x, acc[s][0]);
        FMA2(acc[s][1], wreg[s][5].y, h5.y, acc[s][1]);
    }
    float pg[4];
    #pragma unroll
    for (int s = 0; s < 4; s++) {
        unsigned long long v;
        ADD2(v, acc[s][0], acc[s][1]);
        float lo, hi;
        UNPACK2(lo, hi, v);
        pg[s] = lo + hi;
    }

    // 2-stage select-free butterfly (R12-proven)
    float s1a = pg[0] + __shfl_xor_sync(0xffffffffu, pg[1], 1);
    float s1b = pg[2] + __shfl_xor_sync(0xffffffffu, pg[3], 1);
    float z   = (s1a + pre) + __shfl_xor_sync(0xffffffffu, s1b, 2);

    // activation: sigmoid lanes -> 1 - r ; gate-2 lane -> 2log2e*(1 - 2r)
    float e   = ex2_fast(z);
    float r   = rcp_fast(e + 1.0f);
    float act = fmaf(Aq, r, Bq);

    // gather i, f, g, o of this unit (4 parallel shfls; g pre-scaled by 2log2e)
    float iv = __shfl_sync(0xffffffffu, act, base);
    float fv = __shfl_sync(0xffffffffu, act, base + 1);
    float gv = __shfl_sync(0xffffffffu, act, base + 2);
    float ov = __shfl_sync(0xffffffffu, act, base + 3);

    // redundant branchless update; C = 2log2e*c recurrence
    float m2o = -2.0f * ov;                 // off the critical chain
    C = fmaf(fv, C, iv * gv);
    float e2 = ex2_fast(C);
    float hc = fmaf(m2o, rcp_fast(e2 + 1.0f), ov);
    hout[u] = hc;               // 4 sublanes, same address (benign)
    stg_pred(q, hist_t + u, hc);// q==0 sublane -> history (fire-and-forget)
}

__global__ void __launch_bounds__(NTHR, 1)
lstm_persistent_kernel(const float* __restrict__ x,
                       const float* __restrict__ w_ih,
                       const float* __restrict__ w_hh,
                       const float* __restrict__ b_ih,
                       const float* __restrict__ b_hh,
                       const float* __restrict__ w_out,
                       const float* __restrict__ b_out,
                       float* __restrict__ out)
{
    __shared__ __align__(16) float x_s[TLEN];      // 32 KB: whole input row
    __shared__ __align__(16) float h_s[2][HDIM];   // ping-pong hidden state

    const int tid  = threadIdx.x;
    const int b    = blockIdx.x;
    const int wid  = tid >> 5;
    const int lane = tid & 31;

    {   // stage whole x row, coalesced float4
        const float4* xg = (const float4*)(x + (size_t)b * TLEN);
        float4* xs = (float4*)x_s;
        for (int i = tid; i < TLEN / 4; i += NTHR) xs[i] = xg[i];
    }
    if (tid < HDIM) { h_s[0][tid] = 0.0f; h_s[1][tid] = 0.0f; }

    const int u = 8 * wid + (lane >> 2);   // hidden unit 0..95
    const int q = lane & 3;                // h-quarter; also final gate id

    // XOR-permuted weight slots: slot s = gate (q^s), unit u, cols [24q,24q+24),
    // prescaled into log2 domain per that gate.
    ulonglong2 wreg[4][6];
    #pragma unroll
    for (int s = 0; s < 4; s++) {
        const int g = q ^ s;
        const float sg = (g == 2) ? 2.0f * LOG2E : LOG2E;
        const float4* wr = (const float4*)(w_hh + (size_t)(g * HDIM + u) * HDIM + 24 * q);
        #pragma unroll
        for (int j = 0; j < 6; j++) {
            float4 t = wr[j];
            t.x *= sg; t.y *= sg; t.z *= sg; t.w *= sg;
            ulonglong2 pk;
            memcpy(&pk, &t, 16);
            wreg[s][j] = pk;
        }
    }
    const float sq = (q == 2) ? 2.0f * LOG2E : LOG2E;
    const int row = q * HDIM + u;
    const float wi   = w_ih[row] * sq;
    const float bias = (b_ih[row] + b_hh[row]) * sq;
    // activation constants: sigmoid lanes act = 1 - r; gate-2 act = 2log2e*(1-2r)
    const float Aq = (q == 2) ? -4.0f * LOG2E : -1.0f;
    const float Bq = (q == 2) ?  2.0f * LOG2E :  1.0f;
    const int  base = lane & ~3;

    float* histb = g_hist + (size_t)b * TLEN * HDIM;

    __syncthreads();   // x_s, h init, weights ready

    // ---------------- recurrence: 12 warps, 1 barrier/step ----------------
    {
        const float* hin0 = h_s[0] + 24 * q;
        const float* hin1 = h_s[1] + 24 * q;
        float C = 0.0f;
        #pragma unroll 1
        for (int t = 0; t < TLEN; t += 2) {
            float2 xx = *(const float2*)(x_s + t);      // one LDS.64 per pair
            float pre0 = fmaf(xx.x, wi, bias);
            float pre1 = fmaf(xx.y, wi, bias);
            lstm_step(hin0, h_s[1], histb + (size_t)t * HDIM, pre0,
                      wreg, Aq, Bq, base, u, q, C);
            cta_bar();
            lstm_step(hin1, h_s[0], histb + (size_t)(t + 1) * HDIM, pre1,
                      wreg, Aq, Bq, base, u, q, C);
            cta_bar();
        }
    }

    __syncthreads();   // all h history visible CTA-wide

    // ---------------- y post-pass: warp per timestep ----------------------
    // out[b][t] = <w_out, h(t)> + b_out ; hist row is 96 consecutive floats.
    {
        const float wo = w_out[lane & 31 % 32];  // w_out[lane]
        const float wo0 = w_out[lane];
        const float wo1 = w_out[lane + 32];
        const float wo2 = w_out[lane + 64];
        const float bo  = b_out[0];
        float* outrow = out + (size_t)b * TLEN;
        (void)wo;
        #pragma unroll 1
        for (int t = wid; t < TLEN; t += 12) {
            const float* hr = histb + (size_t)t * HDIM;
            float part = hr[lane] * wo0 + hr[lane + 32] * wo1 + hr[lane + 64] * wo2;
            part += __shfl_xor_sync(0xffffffffu, part, 16);
            part += __shfl_xor_sync(0xffffffffu, part, 8);
            part += __shfl_xor_sync(0xffffffffu, part, 4);
            part += __shfl_xor_sync(0xffffffffu, part, 2);
            part += __shfl_xor_sync(0xffffffffu, part, 1);
            if (lane == 0) outrow[t] = part + bo;
        }
    }
}

extern "C" void kernel_launch(void* const* d_in, const int* in_sizes, int n_in,
                              void* d_out, int out_size)
{
    const float* x     = (const float*)d_in[0];
    const float* w_ih  = (const float*)d_in[1];
    const float* w_hh  = (const float*)d_in[2];
    const float* b_ih  = (const float*)d_in[3];
    const float* b_hh  = (const float*)d_in[4];
    const float* w_out = (const float*)d_in[5];
    const float* b_out = (const float*)d_in[6];
    float* out = (float*)d_out;

    lstm_persistent_kernel<<<BATCH, NTHR>>>(x, w_ih, w_hh, b_ih, b_hh,
                                            w_out, b_out, out);
}

// round 15
// speedup vs baseline: 1.0902x; 1.0902x over previous
#include <cuda_runtime.h>
#include <string.h>

#define BATCH 128
#define TLEN  8192
#define HDIM  96
#define NTHR  800   // 24 gate warps (6/SMSP) + 1 output warp

// Packed fp32x2 FMA (Blackwell): rt=2/SMSP, 2 MACs per issue.
#define FMA2(d, a, b, c) \
    asm("fma.rn.f32x2 %0, %1, %2, %3;" : "=l"(d) : "l"(a), "l"(b), "l"(c))
#define UNPACK2(lo, hi, v) \
    asm("mov.b64 {%0, %1}, %2;" : "=f"(lo), "=f"(hi) : "l"(v))

__device__ __forceinline__ float ex2_fast(float x) {
    float y; asm("ex2.approx.f32 %0, %1;" : "=f"(y) : "f"(x)); return y;
}
__device__ __forceinline__ float rcp_fast(float x) {
    float y; asm("rcp.approx.f32 %0, %1;" : "=f"(y) : "f"(x)); return y;
}
__device__ __forceinline__ void cta_bar() {
    asm volatile("bar.sync 0;" ::: "memory");
}

#define LOG2E 1.4426950408889634f

// One LSTM step, eighth-split XOR layout.
// Lane (unit uu, eighth e): slot s = partial of gate ((e&3)^s) over cols [12e,12e+12).
// Reduction (select-free):
//   s1a = pg0 + shfl_xor(pg1,1)  -> gate (e&3)   over eighths {e, e^1}
//   s1b = pg2 + shfl_xor(pg3,1)  -> gate (e&3)^2 over eighths {e, e^1}
//   s2  = s1a + shfl_xor(s1b,2)  -> gate (e&3)   over {e,e^1,e^2,e^3}
//   z   = s2 + shfl_xor(s2,4) + pre  (lanes e, e^4 share gate & pre; pre added once)
__device__ __forceinline__ void lstm_step(
    const float* __restrict__ hin,   // h_s[p] + 12*e
    float* __restrict__ hout, float pre,
    const ulonglong2 (&wreg)[4][3], float Aq, float Bq,
    int base, int u, float& C)
{
    const ulonglong2* hq = (const ulonglong2*)hin;
    ulonglong2 h0 = hq[0], h1 = hq[1], h2v = hq[2];

    unsigned long long acc[4];
    #pragma unroll
    for (int s = 0; s < 4; s++) acc[s] = 0ull;
    #pragma unroll
    for (int s = 0; s < 4; s++) {
        FMA2(acc[s], wreg[s][0].x, h0.x,  acc[s]);
        FMA2(acc[s], wreg[s][0].y, h0.y,  acc[s]);
        FMA2(acc[s], wreg[s][1].x, h1.x,  acc[s]);
        FMA2(acc[s], wreg[s][1].y, h1.y,  acc[s]);
        FMA2(acc[s], wreg[s][2].x, h2v.x, acc[s]);
        FMA2(acc[s], wreg[s][2].y, h2v.y, acc[s]);
    }
    float pg[4];
    #pragma unroll
    for (int s = 0; s < 4; s++) {
        float lo, hi;
        UNPACK2(lo, hi, acc[s]);
        pg[s] = lo + hi;
    }

    float s1a = pg[0] + __shfl_xor_sync(0xffffffffu, pg[1], 1);
    float s1b = pg[2] + __shfl_xor_sync(0xffffffffu, pg[3], 1);
    float s2  = s1a + __shfl_xor_sync(0xffffffffu, s1b, 2);
    float z   = (s2 + pre) + __shfl_xor_sync(0xffffffffu, s2, 4);

    // activation: sigmoid lanes -> 1 - r ; gate-2 lanes -> 2log2e*(1 - 2r)
    float e   = ex2_fast(z);
    float r   = rcp_fast(e + 1.0f);
    float act = fmaf(Aq, r, Bq);

    // gather i, f, g, o of this unit (lanes base+0..3 own gates 0..3)
    float iv = __shfl_sync(0xffffffffu, act, base);
    float fv = __shfl_sync(0xffffffffu, act, base + 1);
    float gv = __shfl_sync(0xffffffffu, act, base + 2);
    float ov = __shfl_sync(0xffffffffu, act, base + 3);

    // redundant branchless update (8 lanes identical); C = 2log2e*c domain
    float m2o = -2.0f * ov;
    C = fmaf(fv, C, iv * gv);
    float e2 = ex2_fast(C);
    float hc = fmaf(m2o, rcp_fast(e2 + 1.0f), ov);
    hout[u] = hc;   // 8 lanes store identical value to the same address (benign)
}

__global__ void __launch_bounds__(NTHR, 1)
lstm_persistent_kernel(const float* __restrict__ x,
                       const float* __restrict__ w_ih,
                       const float* __restrict__ w_hh,
                       const float* __restrict__ b_ih,
                       const float* __restrict__ b_hh,
                       const float* __restrict__ w_out,
                       const float* __restrict__ b_out,
                       float* __restrict__ out)
{
    __shared__ __align__(16) float x_s[TLEN];      // 32 KB: whole input row
    __shared__ __align__(16) float h_s[2][HDIM];   // ping-pong hidden state

    const int tid  = threadIdx.x;
    const int b    = blockIdx.x;
    const int wid  = tid >> 5;
    const int lane = tid & 31;

    {   // stage whole x row, coalesced float4
        const float4* xg = (const float4*)(x + (size_t)b * TLEN);
        float4* xs = (float4*)x_s;
        for (int i = tid; i < TLEN / 4; i += NTHR) xs[i] = xg[i];
    }
    if (tid < HDIM) { h_s[0][tid] = 0.0f; h_s[1][tid] = 0.0f; }

    const bool is_gate = (wid < 24);
    const int uu = lane >> 3;          // unit within warp 0..3
    const int e  = lane & 7;           // eighth index
    const int u  = 4 * wid + uu;       // hidden unit 0..95 (gate warps)
    const int gq = e & 3;              // this lane's final gate id
    const int base = lane & ~7;        // lanes base+0..3 hold gates 0..3

    // Weights: slot s = gate (gq^s), unit u, cols [12e, 12e+12), log2-prescaled.
    ulonglong2 wreg[4][3];
    float wi = 0.0f, bias = 0.0f;
    if (is_gate) {
        #pragma unroll
        for (int s = 0; s < 4; s++) {
            const int g = gq ^ s;
            const float sg = (g == 2) ? 2.0f * LOG2E : LOG2E;
            const float4* wr = (const float4*)(w_hh + (size_t)(g * HDIM + u) * HDIM + 12 * e);
            #pragma unroll
            for (int j = 0; j < 3; j++) {
                float4 t = wr[j];
                t.x *= sg; t.y *= sg; t.z *= sg; t.w *= sg;
                ulonglong2 pk;
                memcpy(&pk, &t, 16);
                wreg[s][j] = pk;
            }
        }
        const float sq = (gq == 2) ? 2.0f * LOG2E : LOG2E;
        const int row = gq * HDIM + u;
        wi   = w_ih[row] * sq;
        bias = (b_ih[row] + b_hh[row]) * sq;
    }
    const float Aq = (gq == 2) ? -4.0f * LOG2E : -1.0f;
    const float Bq = (gq == 2) ?  2.0f * LOG2E :  1.0f;

    float* outrow = out + (size_t)b * TLEN;

    __syncthreads();   // x_s, h init, weights ready

    if (is_gate) {
        // ---- gate warps: uniform loop, unroll 2, 1 barrier/step ----
        const float* hin0 = h_s[0] + 12 * e;
        const float* hin1 = h_s[1] + 12 * e;
        float C = 0.0f;
        #pragma unroll 1
        for (int t = 0; t < TLEN; t += 2) {
            float2 xx = *(const float2*)(x_s + t);
            float pre0 = fmaf(xx.x, wi, bias);
            float pre1 = fmaf(xx.y, wi, bias);
            lstm_step(hin0, h_s[1], pre0, wreg, Aq, Bq, base, u, C);
            cta_bar();
            lstm_step(hin1, h_s[0], pre1, wreg, Aq, Bq, base, u, C);
            cta_bar();
        }
    } else {
        // ---- output warp (wid 24): emit y(t-1) under the matvec shadow ----
        float wo0 = w_out[lane];
        float wo1 = w_out[lane + 32];
        float wo2 = w_out[lane + 64];
        float bo  = b_out[0];

        cta_bar();   // t = 0: nothing to emit yet
        #pragma unroll 1
        for (int t = 1; t < TLEN; t++) {
            const float* hprev = h_s[t & 1];   // h(t-1)
            float part = hprev[lane] * wo0 + hprev[lane + 32] * wo1
                       + hprev[lane + 64] * wo2;
            part += __shfl_xor_sync(0xffffffffu, part, 16);
            part += __shfl_xor_sync(0xffffffffu, part, 8);
            part += __shfl_xor_sync(0xffffffffu, part, 4);
            part += __shfl_xor_sync(0xffffffffu, part, 2);
            part += __shfl_xor_sync(0xffffffffu, part, 1);
            if (lane == 0) outrow[t - 1] = part + bo;
            cta_bar();
        }
        // final y(T-1): h(T-1) lives in h_s[0] (TLEN even)
        const float* hlast = h_s[0];
        float part = hlast[lane] * wo0 + hlast[lane + 32] * wo1
                   + hlast[lane + 64] * wo2;
        part += __shfl_xor_sync(0xffffffffu, part, 16);
        part += __shfl_xor_sync(0xffffffffu, part, 8);
        part += __shfl_xor_sync(0xffffffffu, part, 4);
        part += __shfl_xor_sync(0xffffffffu, part, 2);
        part += __shfl_xor_sync(0xffffffffu, part, 1);
        if (lane == 0) outrow[TLEN - 1] = part + bo;
    }
}

extern "C" void kernel_launch(void* const* d_in, const int* in_sizes, int n_in,
                              void* d_out, int out_size)
{
    const float* x     = (const float*)d_in[0];
    const float* w_ih  = (const float*)d_in[1];
    const float* w_hh  = (const float*)d_in[2];
    const float* b_ih  = (const float*)d_in[3];
    const float* b_hh  = (const float*)d_in[4];
    const float* w_out = (const float*)d_in[5];
    const float* b_out = (const float*)d_in[6];
    float* out = (float*)d_out;

    lstm_persistent_kernel<<<BATCH, NTHR>>>(x, w_ih, w_hh, b_ih, b_hh,
                                            w_out, b_out, out);
}